// round 1
// baseline (speedup 1.0000x reference)
#include <cuda_runtime.h>
#include <cuda_bf16.h>

// Problem constants
#define C_IN   128
#define D_QKV  256
#define N_HEAD 8
#define DKH    32
#define IMG_H  192
#define IMG_W  192
#define NPIX   (IMG_H * IMG_W)   // 36864
#define TEMPER_INV (1.0f / 16.0f)

// Scratch (device globals: allocation-free per harness rules)
__device__ float g_q[D_QKV * NPIX];   // 37.75 MB
__device__ float g_k[D_QKV * NPIX];   // 37.75 MB
__device__ float g_v[D_QKV * NPIX];   // 37.75 MB
__device__ float g_s[NPIX * N_HEAD];  // 1.18 MB, pixel-major [p][h], pre-divided by TEMPER

// ---------------------------------------------------------------------------
// Kernel 1: projection GEMM  C[768, 36864] = W[768,128] @ X[128, 36864]
// BM=128 x BN=128 x BK=16 tiles, 256 threads, 8x8 micro-tile,
// inner product issued as packed fma.rn.f32x2 (full-rate fp32 on sm_103a).
// grid = (288, 6); blockIdx.y selects {q0,q1,k0,k1,v0,v1} 128-row groups.
// ---------------------------------------------------------------------------
#define BM 128
#define BN 128
#define BK 16

__global__ __launch_bounds__(256, 2)
void proj_kernel(const float* __restrict__ x,
                 const float* __restrict__ wq,
                 const float* __restrict__ wk,
                 const float* __restrict__ wv)
{
    const int g = blockIdx.y;                     // 0..5
    const float* W = (g < 2 ? wq : (g < 4 ? wk : wv)) + (g & 1) * (128 * C_IN);
    float*       O = (g < 2 ? g_q : (g < 4 ? g_k : g_v)) + (size_t)(g & 1) * (128 * NPIX);
    const int p0 = blockIdx.x * BN;

    __shared__ float As[BK][BM];   // A transposed: As[k][m]
    __shared__ float Bs[BK][BN];

    const int t  = threadIdx.x;
    const int tm = t >> 4;   // 0..15 -> rows tm*8 .. tm*8+7
    const int tn = t & 15;   // 0..15 -> cols tn*8 .. tn*8+7

    unsigned long long acc[8][4];
#pragma unroll
    for (int i = 0; i < 8; i++)
#pragma unroll
        for (int j = 0; j < 4; j++) acc[i][j] = 0ULL;

    for (int k0 = 0; k0 < C_IN; k0 += BK) {
#pragma unroll
        for (int l = 0; l < 2; l++) {
            const int id = t + l * 256;           // 0..511
            // A tile: 128 rows x 16 k  (512 float4)
            {
                const int row = id >> 2;          // 0..127
                const int kq  = (id & 3) * 4;     // 0,4,8,12
                float4 av = *(const float4*)&W[row * C_IN + k0 + kq];
                As[kq + 0][row] = av.x;
                As[kq + 1][row] = av.y;
                As[kq + 2][row] = av.z;
                As[kq + 3][row] = av.w;
            }
            // B tile: 16 k x 128 pixels (512 float4), fully coalesced
            {
                const int kr = id >> 5;           // 0..15
                const int n4 = (id & 31) * 4;     // 0..124
                float4 bv = *(const float4*)&x[(size_t)(k0 + kr) * NPIX + p0 + n4];
                *(float4*)&Bs[kr][n4] = bv;
            }
        }
        __syncthreads();

#pragma unroll
        for (int kk = 0; kk < BK; kk++) {
            float a[8];
#pragma unroll
            for (int i = 0; i < 8; i++) a[i] = As[kk][tm * 8 + i];
            unsigned long long b2[4];
            const unsigned long long* bp =
                (const unsigned long long*)&Bs[kk][tn * 8];
#pragma unroll
            for (int j = 0; j < 4; j++) b2[j] = bp[j];
#pragma unroll
            for (int i = 0; i < 8; i++) {
                unsigned long long a2;
                asm("mov.b64 %0, {%1, %1};" : "=l"(a2) : "r"(__float_as_uint(a[i])));
#pragma unroll
                for (int j = 0; j < 4; j++)
                    asm("fma.rn.f32x2 %0, %1, %2, %0;"
                        : "+l"(acc[i][j]) : "l"(a2), "l"(b2[j]));
            }
        }
        __syncthreads();
    }

    // Store 8x8 micro-tile (packed low lane = even column, matches memory order)
#pragma unroll
    for (int i = 0; i < 8; i++) {
        float* orow = &O[(size_t)(tm * 8 + i) * NPIX + p0 + tn * 8];
        *(ulonglong2*)(orow)     = make_ulonglong2(acc[i][0], acc[i][1]);
        *(ulonglong2*)(orow + 4) = make_ulonglong2(acc[i][2], acc[i][3]);
    }
}

// ---------------------------------------------------------------------------
// Kernel 2: per-pixel per-head scores  s[p][h] = (sum_{d in head} q*k) / 16
// Pure streaming: 75.5 MB read, 1.18 MB write.
// ---------------------------------------------------------------------------
__global__ __launch_bounds__(256)
void score_kernel()
{
    const int p = blockIdx.x * blockDim.x + threadIdx.x;
    if (p >= NPIX) return;

    float acc[N_HEAD];
#pragma unroll
    for (int h = 0; h < N_HEAD; h++) acc[h] = 0.0f;

#pragma unroll 32
    for (int c = 0; c < D_QKV; c++) {
        const float qv = g_q[(size_t)c * NPIX + p];
        const float kv = g_k[(size_t)c * NPIX + p];
        acc[c >> 5] = fmaf(qv, kv, acc[c >> 5]);
    }

    float4 s0 = make_float4(acc[0] * TEMPER_INV, acc[1] * TEMPER_INV,
                            acc[2] * TEMPER_INV, acc[3] * TEMPER_INV);
    float4 s1 = make_float4(acc[4] * TEMPER_INV, acc[5] * TEMPER_INV,
                            acc[6] * TEMPER_INV, acc[7] * TEMPER_INV);
    *(float4*)&g_s[(size_t)p * N_HEAD]     = s0;
    *(float4*)&g_s[(size_t)p * N_HEAD + 4] = s1;
}

// ---------------------------------------------------------------------------
// Kernel 3: softmax over the 9 region slots + weighted 3x3 gather of v.
// Zero-padding semantics of the reference: OOB slots contribute exp(0) to
// the softmax denominator but zero to the numerator (v = 0 there).
// grid = (IMG_H rows, N_HEAD), 192 threads = one image row per block.
// ---------------------------------------------------------------------------
__global__ __launch_bounds__(192)
void attn_kernel(float* __restrict__ out)
{
    const int xp = threadIdx.x;        // 0..191
    const int y  = blockIdx.x;         // 0..191
    const int h  = blockIdx.y;         // 0..7
    const int p  = y * IMG_W + xp;

    float sc[9];
    int   np[9];
    bool  valid[9];
#pragma unroll
    for (int dy = -1; dy <= 1; dy++) {
#pragma unroll
        for (int dx = -1; dx <= 1; dx++) {
            const int r  = (dy + 1) * 3 + (dx + 1);
            const int ny = y + dy, nx = xp + dx;
            const bool v = (ny >= 0) && (ny < IMG_H) && (nx >= 0) && (nx < IMG_W);
            valid[r] = v;
            np[r]    = ny * IMG_W + nx;
            sc[r]    = v ? g_s[(size_t)(ny * IMG_W + nx) * N_HEAD + h] : 0.0f;
        }
    }

    float m = sc[0];
#pragma unroll
    for (int r = 1; r < 9; r++) m = fmaxf(m, sc[r]);
    float e[9], sum = 0.0f;
#pragma unroll
    for (int r = 0; r < 9; r++) { e[r] = expf(sc[r] - m); sum += e[r]; }
    const float inv = 1.0f / sum;
    float w[9];
#pragma unroll
    for (int r = 0; r < 9; r++) w[r] = e[r] * inv;

    const float* vb = g_v + (size_t)(h * DKH) * NPIX;
    float*       ob = out + (size_t)(h * DKH) * NPIX;
#pragma unroll 4
    for (int c = 0; c < DKH; c++) {
        float acc = 0.0f;
#pragma unroll
        for (int r = 0; r < 9; r++) {
            const float vv = valid[r] ? vb[(size_t)c * NPIX + np[r]] : 0.0f;
            acc = fmaf(w[r], vv, acc);
        }
        ob[(size_t)c * NPIX + p] = acc;
    }
}

// ---------------------------------------------------------------------------
extern "C" void kernel_launch(void* const* d_in, const int* in_sizes, int n_in,
                              void* d_out, int out_size)
{
    const float* x  = (const float*)d_in[0];   // [128, 192, 192]
    const float* wq = (const float*)d_in[1];   // [256, 128]
    const float* wk = (const float*)d_in[2];
    const float* wv = (const float*)d_in[3];
    float* out = (float*)d_out;                // [256, 192, 192]

    dim3 pgrid(NPIX / BN, 6);                  // 288 x 6
    proj_kernel<<<pgrid, 256>>>(x, wq, wk, wv);

    score_kernel<<<NPIX / 256, 256>>>();       // 144 blocks

    dim3 agrid(IMG_H, N_HEAD);                 // 192 x 8
    attn_kernel<<<agrid, 192>>>(out);
}

// round 3
// speedup vs baseline: 1.6003x; 1.6003x over previous
#include <cuda_runtime.h>
#include <cuda_bf16.h>
#include <cstdint>

// ---------------------------------------------------------------- constants
#define C_IN   128
#define N_HEAD 8
#define IMG_H  192
#define IMG_W  192
#define NPIX   (IMG_H * IMG_W)          // 36864
#define TEMPER_INV (1.0f / 16.0f)

// scratch (device globals — allocation-free per harness rules)
__device__ float g_v[256 * NPIX];       // 37.75 MB
__device__ float g_s[NPIX * N_HEAD];    // 1.18 MB, [p][h], pre-divided by 16

// ---------------------------------------------------------------- SMEM map (bytes)
// All tiles stored [row][k] bf16, 256B rows, XOR-swizzled 16B chunks.
#define SM_BT_HI 0          // X^T tile: 128 pix x 128 k
#define SM_BT_LO 32768
#define SM_A0_HI 65536      // W tile 0: 128 out x 128 k
#define SM_A0_LO 98304
#define SM_A1_HI 131072     // W tile 1 (qk CTAs only)
#define SM_A1_LO 163840
#define SM_TOTAL 196608     // 192 KB dynamic

__device__ __forceinline__ uint32_t smem_u32(const void* p) {
    uint32_t a;
    asm("{ .reg .u64 t; cvta.to.shared.u64 t, %1; cvt.u32.u64 %0, t; }" : "=r"(a) : "l"(p));
    return a;
}

// swizzled byte offset of element (row, k) in a [row][k] bf16 tile, 256B rows
__device__ __forceinline__ uint32_t soff(int row, int k) {
    return (uint32_t)(row * 256 + (((k >> 3) ^ (row & 7)) << 4) + (k & 7) * 2);
}

__device__ __forceinline__ void ldsm4(uint32_t r[4], uint32_t addr) {
    asm volatile("ldmatrix.sync.aligned.m8n8.x4.shared.b16 {%0,%1,%2,%3}, [%4];"
                 : "=r"(r[0]), "=r"(r[1]), "=r"(r[2]), "=r"(r[3]) : "r"(addr));
}

__device__ __forceinline__ void mma16816(float c[4], const uint32_t a[4],
                                         uint32_t b0, uint32_t b1) {
    asm volatile(
        "mma.sync.aligned.m16n8k16.row.col.f32.bf16.bf16.f32 "
        "{%0,%1,%2,%3}, {%4,%5,%6,%7}, {%8,%9}, {%0,%1,%2,%3};"
        : "+f"(c[0]), "+f"(c[1]), "+f"(c[2]), "+f"(c[3])
        : "r"(a[0]), "r"(a[1]), "r"(a[2]), "r"(a[3]), "r"(b0), "r"(b1));
}

// fp32 -> bf16 hi + bf16 lo (residual)
__device__ __forceinline__ void split1(float a, uint16_t& h, uint16_t& l) {
    __nv_bfloat16 hb = __float2bfloat16(a);
    __nv_bfloat16 lb = __float2bfloat16(a - __bfloat162float(hb));
    h = __bfloat16_as_ushort(hb);
    l = __bfloat16_as_ushort(lb);
}

// load W[128 x 128] fp32 (row-major, k contig) -> SMEM hi/lo tiles
__device__ __forceinline__ void loadW(const float* __restrict__ Wg, char* smem,
                                      int hiOff, int loOff, int tid) {
#pragma unroll 2
    for (int i = tid; i < 128 * 32; i += 512) {
        const int row = i >> 5;
        const int k4  = (i & 31) * 4;
        float4 w = *(const float4*)&Wg[row * C_IN + k4];
        uint16_t h0, l0, h1, l1, h2, l2, h3, l3;
        split1(w.x, h0, l0); split1(w.y, h1, l1);
        split1(w.z, h2, l2); split1(w.w, h3, l3);
        const uint32_t off = soff(row, k4);
        *(uint2*)(smem + hiOff + off) =
            make_uint2((uint32_t)h0 | ((uint32_t)h1 << 16), (uint32_t)h2 | ((uint32_t)h3 << 16));
        *(uint2*)(smem + loOff + off) =
            make_uint2((uint32_t)l0 | ((uint32_t)l1 << 16), (uint32_t)l2 | ((uint32_t)l3 << 16));
    }
}

// one split-pass: C[2][4][4] += A(aBase) @ B(bBase)^T over K=128
__device__ __forceinline__ void gemm_pass(uint32_t aBase, uint32_t bBase,
                                          float C[2][4][4],
                                          int rowA, int kA, int rowB, int kB,
                                          int wr, int wc) {
#pragma unroll
    for (int k0 = 0; k0 < 8; k0++) {
        uint32_t a[2][4];
#pragma unroll
        for (int tm = 0; tm < 2; tm++)
            ldsm4(a[tm], aBase + soff(wr * 32 + tm * 16 + rowA, k0 * 16 + kA));
        uint32_t b[2][4];
#pragma unroll
        for (int tp = 0; tp < 2; tp++)
            ldsm4(b[tp], bBase + soff(wc * 32 + tp * 16 + rowB, k0 * 16 + kB));
#pragma unroll
        for (int tm = 0; tm < 2; tm++)
#pragma unroll
            for (int tn = 0; tn < 4; tn++)
                mma16816(C[tm][tn], a[tm], b[tn >> 1][(tn & 1) * 2], b[tn >> 1][(tn & 1) * 2 + 1]);
    }
}

// full-precision product via 3 split passes (hh + hl + lh)
__device__ __forceinline__ void gemm_full(uint32_t aHi, uint32_t aLo,
                                          uint32_t bHi, uint32_t bLo,
                                          float C[2][4][4],
                                          int rowA, int kA, int rowB, int kB,
                                          int wr, int wc) {
    gemm_pass(aHi, bHi, C, rowA, kA, rowB, kB, wr, wc);
    gemm_pass(aHi, bLo, C, rowA, kA, rowB, kB, wr, wc);
    gemm_pass(aLo, bHi, C, rowA, kA, rowB, kB, wr, wc);
}

// ---------------------------------------------------------------- kernel 1
// grid (288, 4), 512 threads.
//   type 0: q[0:128] & k[0:128]  -> s heads 0..3 (fused epilogue)
//   type 1: q[128:256] & k[128:256] -> s heads 4..7
//   type 2: v[0:128]   -> g_v
//   type 3: v[128:256] -> g_v
__global__ void __launch_bounds__(512, 1)
proj_fused(const float* __restrict__ x,
           const float* __restrict__ wq,
           const float* __restrict__ wk,
           const float* __restrict__ wv)
{
    extern __shared__ char smem[];
    const uint32_t sb = smem_u32(smem);
    const int tid  = threadIdx.x;
    const int lane = tid & 31;
    const int wid  = tid >> 5;
    const int wr   = wid >> 2;   // 0..3: 32-channel row group (one head)
    const int wc   = wid & 3;    // 0..3: 32-pixel col group
    const int type = blockIdx.y;
    const int p0   = blockIdx.x * 128;

    // lane components for ldmatrix addressing
    const int rowA = ((lane >> 3) & 1) * 8 + (lane & 7);
    const int kA   = (lane >> 4) * 8;
    const int rowB = ((lane >> 4) & 1) * 8 + (lane & 7);
    const int kB   = ((lane >> 3) & 1) * 8;

    // ---- load X^T tile (pix-major, k contig) as bf16 hi/lo
    {
        const float* xp = x + p0;
#pragma unroll 4
        for (int i = tid; i < 128 * 64; i += 512) {
            const int pix = i & 127;
            const int c2  = (i >> 7) * 2;
            float f0 = xp[(size_t)c2 * NPIX + pix];
            float f1 = xp[(size_t)(c2 + 1) * NPIX + pix];
            uint16_t h0, l0, h1, l1;
            split1(f0, h0, l0); split1(f1, h1, l1);
            const uint32_t off = soff(pix, c2);
            *(uint32_t*)(smem + SM_BT_HI + off) = (uint32_t)h0 | ((uint32_t)h1 << 16);
            *(uint32_t*)(smem + SM_BT_LO + off) = (uint32_t)l0 | ((uint32_t)l1 << 16);
        }
    }

    // ---- load weight tile(s)
    if (type < 2) {
        loadW(wq + (size_t)type * 128 * C_IN, smem, SM_A0_HI, SM_A0_LO, tid);
        loadW(wk + (size_t)type * 128 * C_IN, smem, SM_A1_HI, SM_A1_LO, tid);
    } else {
        loadW(wv + (size_t)(type - 2) * 128 * C_IN, smem, SM_A0_HI, SM_A0_LO, tid);
    }
    __syncthreads();

    // ---- first GEMM (q or v)
    float C0[2][4][4];
#pragma unroll
    for (int i = 0; i < 2; i++)
#pragma unroll
        for (int j = 0; j < 4; j++)
#pragma unroll
            for (int m = 0; m < 4; m++) C0[i][j][m] = 0.0f;

    gemm_full(sb + SM_A0_HI, sb + SM_A0_LO, sb + SM_BT_HI, sb + SM_BT_LO,
              C0, rowA, kA, rowB, kB, wr, wc);

    if (type < 2) {
        // ---- second GEMM (k)
        float C1[2][4][4];
#pragma unroll
        for (int i = 0; i < 2; i++)
#pragma unroll
            for (int j = 0; j < 4; j++)
#pragma unroll
                for (int m = 0; m < 4; m++) C1[i][j][m] = 0.0f;

        gemm_full(sb + SM_A1_HI, sb + SM_A1_LO, sb + SM_BT_HI, sb + SM_BT_LO,
                  C1, rowA, kA, rowB, kB, wr, wc);

        // ---- fused score epilogue: s[p][h] = (q . k over the 32-chan head) / 16
        const int h = type * 4 + wr;
#pragma unroll
        for (int tn = 0; tn < 4; tn++) {
            float s0 = 0.0f, s1 = 0.0f;
#pragma unroll
            for (int tm = 0; tm < 2; tm++) {
                s0 += C0[tm][tn][0] * C1[tm][tn][0] + C0[tm][tn][2] * C1[tm][tn][2];
                s1 += C0[tm][tn][1] * C1[tm][tn][1] + C0[tm][tn][3] * C1[tm][tn][3];
            }
            // reduce across lane bits 2..4 (the 8 row groups of the fragment)
#pragma unroll
            for (int d = 4; d < 32; d <<= 1) {
                s0 += __shfl_xor_sync(0xffffffffu, s0, d);
                s1 += __shfl_xor_sync(0xffffffffu, s1, d);
            }
            if (lane < 4) {
                const int pix = p0 + wc * 32 + tn * 8 + lane * 2;
                g_s[(size_t)pix * 8 + h]       = s0 * TEMPER_INV;
                g_s[(size_t)(pix + 1) * 8 + h] = s1 * TEMPER_INV;
            }
        }
    } else {
        // ---- v epilogue: store channel-major
        const int cb = (type - 2) * 128;
#pragma unroll
        for (int tm = 0; tm < 2; tm++)
#pragma unroll
            for (int tn = 0; tn < 4; tn++) {
                const int chan = cb + wr * 32 + tm * 16 + (lane >> 2);
                const int pix  = p0 + wc * 32 + tn * 8 + (lane & 3) * 2;
                *(float2*)&g_v[(size_t)chan * NPIX + pix] =
                    make_float2(C0[tm][tn][0], C0[tm][tn][1]);
                *(float2*)&g_v[(size_t)(chan + 8) * NPIX + pix] =
                    make_float2(C0[tm][tn][2], C0[tm][tn][3]);
            }
    }
}

// ---------------------------------------------------------------- kernel 2
// softmax over 9 region slots + weighted 3x3 gather of v.
// OOB slots contribute exp(0) to the denominator, 0 to the numerator.
__global__ void __launch_bounds__(192)
attn_kernel(float* __restrict__ out)
{
    const int xp = threadIdx.x;
    const int y  = blockIdx.x;
    const int h  = blockIdx.y;
    const int p  = y * IMG_W + xp;

    float sc[9];
    int   np[9];
    bool  valid[9];
#pragma unroll
    for (int dy = -1; dy <= 1; dy++) {
#pragma unroll
        for (int dx = -1; dx <= 1; dx++) {
            const int r  = (dy + 1) * 3 + (dx + 1);
            const int ny = y + dy, nx = xp + dx;
            const bool v = (ny >= 0) && (ny < IMG_H) && (nx >= 0) && (nx < IMG_W);
            valid[r] = v;
            np[r]    = ny * IMG_W + nx;
            sc[r]    = v ? g_s[(size_t)(ny * IMG_W + nx) * N_HEAD + h] : 0.0f;
        }
    }

    float m = sc[0];
#pragma unroll
    for (int r = 1; r < 9; r++) m = fmaxf(m, sc[r]);
    float e[9], sum = 0.0f;
#pragma unroll
    for (int r = 0; r < 9; r++) { e[r] = __expf(sc[r] - m); sum += e[r]; }
    const float inv = 1.0f / sum;
    float w[9];
#pragma unroll
    for (int r = 0; r < 9; r++) w[r] = e[r] * inv;

    const float* vb = g_v + (size_t)(h * 32) * NPIX;
    float*       ob = out + (size_t)(h * 32) * NPIX;
#pragma unroll 4
    for (int c = 0; c < 32; c++) {
        float acc = 0.0f;
#pragma unroll
        for (int r = 0; r < 9; r++) {
            const float vv = valid[r] ? vb[(size_t)c * NPIX + np[r]] : 0.0f;
            acc = fmaf(w[r], vv, acc);
        }
        ob[(size_t)c * NPIX + p] = acc;
    }
}

// ---------------------------------------------------------------- launch
extern "C" void kernel_launch(void* const* d_in, const int* in_sizes, int n_in,
                              void* d_out, int out_size)
{
    const float* x  = (const float*)d_in[0];
    const float* wq = (const float*)d_in[1];
    const float* wk = (const float*)d_in[2];
    const float* wv = (const float*)d_in[3];
    float* out = (float*)d_out;

    cudaFuncSetAttribute(proj_fused, cudaFuncAttributeMaxDynamicSharedMemorySize, SM_TOTAL);

    dim3 pgrid(NPIX / 128, 4);               // 288 x 4
    proj_fused<<<pgrid, 512, SM_TOTAL>>>(x, wq, wk, wv);

    dim3 agrid(IMG_H, N_HEAD);               // 192 x 8
    attn_kernel<<<agrid, 192>>>(out);
}

// round 5
// speedup vs baseline: 2.5421x; 1.5885x over previous
#include <cuda_runtime.h>
#include <cstdint>

// ---------------------------------------------------------------- constants
#define C_IN   128
#define N_HEAD 8
#define IMG_H  192
#define IMG_W  192
#define NPIX   (IMG_H * IMG_W)     // 36864
#define PW     200                 // padded v row stride (floats)
#define PH     194                 // padded rows
#define PVP    (PH * PW)           // 38800 floats per channel plane
#define SW     194                 // padded s row width
#define TEMPER_INV (1.0f / 16.0f)

// scratch (device globals — allocation-free per harness rules)
__device__ float g_v[256 * PVP];          // 39.7 MB, padded, x-offset +2
__device__ float g_s[PH * SW * N_HEAD];   // 1.2 MB,  padded, x-offset +1

// ---------------------------------------------------------------- SMEM map
#define SM_X     0            // X^T B-fragments: 64 KB
#define SM_W0    65536        // W A-fragments buffer 0: 64 KB
#define SM_W1    131072       // W A-fragments buffer 1: 64 KB
#define SM_TOTAL 196608

// ---------------------------------------------------------------- primitives
__device__ __forceinline__ uint32_t f2tf32(float f) {
    uint32_t r;
    asm("cvt.rna.tf32.f32 %0, %1;" : "=r"(r) : "f"(f));
    return r;
}

__device__ __forceinline__ void mma_tf32(float c[4], const uint32_t a[4],
                                         uint32_t b0, uint32_t b1) {
    asm volatile(
        "mma.sync.aligned.m16n8k8.row.col.f32.tf32.tf32.f32 "
        "{%0,%1,%2,%3}, {%4,%5,%6,%7}, {%8,%9}, {%0,%1,%2,%3};"
        : "+f"(c[0]), "+f"(c[1]), "+f"(c[2]), "+f"(c[3])
        : "r"(a[0]), "r"(a[1]), "r"(a[2]), "r"(a[3]), "r"(b0), "r"(b1));
}

// W[128x128] fp32 (k-contig) -> A-fragment-major smem (one uint4 per frag slot).
// Frag slot (rowgrp, kstep, lane): regs a0..a3 = rows {r,r+8} x cols {c,c+4},
// r = lane>>2, c = lane&3, addr = ((rowgrp*16+kstep)*32+lane)*16.
__device__ __forceinline__ void loadW_frag(const float* __restrict__ Wg,
                                           char* buf, int tid) {
    const int lane = tid & 31, kstep = tid >> 5;      // kstep 0..15
    const int r = lane >> 2, c = lane & 3;
#pragma unroll
    for (int rowgrp = 0; rowgrp < 8; rowgrp++) {
        const float* p = Wg + (rowgrp * 16 + r) * C_IN + kstep * 8 + c;
        uint32_t a0 = f2tf32(p[0]);
        uint32_t a1 = f2tf32(p[8 * C_IN]);
        uint32_t a2 = f2tf32(p[4]);
        uint32_t a3 = f2tf32(p[8 * C_IN + 4]);
        *(uint4*)(buf + ((rowgrp * 16 + kstep) * 32 + lane) * 16) =
            make_uint4(a0, a1, a2, a3);
    }
}

// X^T tile (128 pixels starting p0, 128 chans) -> B-fragment-major smem.
// Frag slot (pixgrp, kstep, lane): regs b0,b1 = (k=lane&3 {,+4}, n=lane>>2),
// addr = ((pixgrp*16+kstep)*32+lane)*8.
__device__ __forceinline__ void loadX_frag(const float* __restrict__ xt,
                                           char* buf, int tid) {
    const int lane = tid & 31, kstep = tid >> 5;
    const int n = lane >> 2, kc = lane & 3;
#pragma unroll
    for (int pixgrp = 0; pixgrp < 16; pixgrp++) {
        const int pix = pixgrp * 8 + n;
        const int ch  = kstep * 8 + kc;
        uint32_t b0 = f2tf32(xt[(size_t)ch * NPIX + pix]);
        uint32_t b1 = f2tf32(xt[(size_t)(ch + 4) * NPIX + pix]);
        *(uint2*)(buf + ((pixgrp * 16 + kstep) * 32 + lane) * 8) = make_uint2(b0, b1);
    }
}

// C[2][4][4] += A(Abuf)[128x128] @ B(Bbuf)[128pix x 128k]^T for this warp tile.
__device__ __forceinline__ void gemm_tf32(const char* Abuf, const char* Bbuf,
                                          float C[2][4][4],
                                          int wr, int wc, int lane) {
#pragma unroll 4
    for (int kstep = 0; kstep < 16; kstep++) {
        uint32_t a[2][4];
#pragma unroll
        for (int tm = 0; tm < 2; tm++)
            *(uint4*)a[tm] =
                *(const uint4*)(Abuf + (((wr * 2 + tm) * 16 + kstep) * 32 + lane) * 16);
        uint32_t b[4][2];
#pragma unroll
        for (int tn = 0; tn < 4; tn++)
            *(uint2*)b[tn] =
                *(const uint2*)(Bbuf + (((wc * 4 + tn) * 16 + kstep) * 32 + lane) * 8);
#pragma unroll
        for (int tm = 0; tm < 2; tm++)
#pragma unroll
            for (int tn = 0; tn < 4; tn++)
                mma_tf32(C[tm][tn], a[tm], b[tn][0], b[tn][1]);
    }
}

__device__ __forceinline__ void zeroC(float C[2][4][4]) {
#pragma unroll
    for (int i = 0; i < 2; i++)
#pragma unroll
        for (int j = 0; j < 4; j++)
#pragma unroll
            for (int m = 0; m < 4; m++) C[i][j][m] = 0.0f;
}

// fused score epilogue: s[p][h] = (q . k over the 32-chan head) / 16 -> padded g_s
__device__ __forceinline__ void epi_s(const float C0[2][4][4], const float C1[2][4][4],
                                      int h, int p0, int wc, int lane) {
#pragma unroll
    for (int tn = 0; tn < 4; tn++) {
        float s0 = 0.0f, s1 = 0.0f;
#pragma unroll
        for (int tm = 0; tm < 2; tm++) {
            s0 += C0[tm][tn][0] * C1[tm][tn][0] + C0[tm][tn][2] * C1[tm][tn][2];
            s1 += C0[tm][tn][1] * C1[tm][tn][1] + C0[tm][tn][3] * C1[tm][tn][3];
        }
#pragma unroll
        for (int d = 4; d < 32; d <<= 1) {
            s0 += __shfl_xor_sync(0xffffffffu, s0, d);
            s1 += __shfl_xor_sync(0xffffffffu, s1, d);
        }
        if (lane < 4) {
            const int pix = p0 + wc * 32 + tn * 8 + lane * 2;
            const int y = pix / IMG_W, xx = pix - y * IMG_W;     // xx even
            const size_t sp = ((size_t)(y + 1) * SW + (xx + 1)) * 8 + h;
            g_s[sp]     = s0 * TEMPER_INV;
            g_s[sp + 8] = s1 * TEMPER_INV;
        }
    }
}

// v epilogue: store to padded channel planes (x-offset +2 keeps 8B alignment)
__device__ __forceinline__ void sto_v(const float C[2][4][4], int cb,
                                      int p0, int wr, int wc, int lane) {
#pragma unroll
    for (int tm = 0; tm < 2; tm++)
#pragma unroll
        for (int tn = 0; tn < 4; tn++) {
            const int chan = cb + wr * 32 + tm * 16 + (lane >> 2);
            const int pix  = p0 + wc * 32 + tn * 8 + (lane & 3) * 2;
            const int y = pix / IMG_W, xx = pix - y * IMG_W;     // xx even
            float* vp = g_v + (size_t)chan * PVP + (size_t)(y + 1) * PW + (xx + 2);
            *(float2*)vp = make_float2(C[tm][tn][0], C[tm][tn][1]);
            *(float2*)(vp + (size_t)8 * PVP) = make_float2(C[tm][tn][2], C[tm][tn][3]);
        }
}

// ---------------------------------------------------------------- kernel 0
// zero the padded borders of g_v (per-channel blocks) and g_s (block 256)
__global__ void __launch_bounds__(256)
zero_borders()
{
    const int b = blockIdx.x, t = threadIdx.x;
    if (b < 256) {
        float* vp = g_v + (size_t)b * PVP;
        if (t < 200) { vp[t] = 0.0f; vp[(size_t)193 * PW + t] = 0.0f; }
        if (t < 192) {
            vp[(size_t)(t + 1) * PW + 1]   = 0.0f;
            vp[(size_t)(t + 1) * PW + 194] = 0.0f;
        }
    } else {
        for (int i = t; i < SW * 8; i += 256) {
            g_s[i] = 0.0f;                              // row 0
            g_s[(size_t)193 * SW * 8 + i] = 0.0f;       // row 193
        }
        for (int i = t; i < 192 * 8; i += 256) {
            const int y = i >> 3, h = i & 7;
            g_s[((size_t)(y + 1) * SW + 0)   * 8 + h] = 0.0f;
            g_s[((size_t)(y + 1) * SW + 193) * 8 + h] = 0.0f;
        }
    }
}

// ---------------------------------------------------------------- kernel 1
// one CTA per 128-pixel tile; 6 double-buffered weight stages:
// wq0, wk0 (-> s heads 0-3), wq1, wk1 (-> s heads 4-7), wv0, wv1 (-> g_v)
__global__ void __launch_bounds__(512, 1)
proj_fused(const float* __restrict__ x,
           const float* __restrict__ wq,
           const float* __restrict__ wk,
           const float* __restrict__ wv)
{
    extern __shared__ char smem[];
    const int tid  = threadIdx.x;
    const int lane = tid & 31;
    const int wid  = tid >> 5;
    const int wr   = wid >> 2;     // 32-channel row group
    const int wc   = wid & 3;      // 32-pixel col group
    const int p0   = blockIdx.x * 128;

    loadX_frag(x + p0, smem + SM_X, tid);
    loadW_frag(wq, smem + SM_W0, tid);
    __syncthreads();

    float C0[2][4][4], C1[2][4][4];

    // stage 0: q chans 0..127  (buf0); prefetch wk0 -> buf1
    loadW_frag(wk, smem + SM_W1, tid);
    zeroC(C0);
    gemm_tf32(smem + SM_W0, smem + SM_X, C0, wr, wc, lane);
    __syncthreads();

    // stage 1: k chans 0..127  (buf1); prefetch wq1 -> buf0
    loadW_frag(wq + 16384, smem + SM_W0, tid);
    zeroC(C1);
    gemm_tf32(smem + SM_W1, smem + SM_X, C1, wr, wc, lane);
    epi_s(C0, C1, wr, p0, wc, lane);
    __syncthreads();

    // stage 2: q chans 128..255 (buf0); prefetch wk1 -> buf1
    loadW_frag(wk + 16384, smem + SM_W1, tid);
    zeroC(C0);
    gemm_tf32(smem + SM_W0, smem + SM_X, C0, wr, wc, lane);
    __syncthreads();

    // stage 3: k chans 128..255 (buf1); prefetch wv0 -> buf0
    loadW_frag(wv, smem + SM_W0, tid);
    zeroC(C1);
    gemm_tf32(smem + SM_W1, smem + SM_X, C1, wr, wc, lane);
    epi_s(C0, C1, 4 + wr, p0, wc, lane);
    __syncthreads();

    // stage 4: v chans 0..127 (buf0); prefetch wv1 -> buf1
    loadW_frag(wv + 16384, smem + SM_W1, tid);
    zeroC(C0);
    gemm_tf32(smem + SM_W0, smem + SM_X, C0, wr, wc, lane);
    sto_v(C0, 0, p0, wr, wc, lane);
    __syncthreads();

    // stage 5: v chans 128..255 (buf1)
    zeroC(C0);
    gemm_tf32(smem + SM_W1, smem + SM_X, C0, wr, wc, lane);
    sto_v(C0, 128, p0, wr, wc, lane);
}

// ---------------------------------------------------------------- kernel 2
// branch-free softmax over 9 region slots + weighted 3x3 gather of padded v
__global__ void __launch_bounds__(192)
attn_kernel(float* __restrict__ out)
{
    const int xx = threadIdx.x;       // 0..191
    const int y  = blockIdx.x;        // 0..191
    const int h  = blockIdx.y;        // 0..7

    const float* sp = g_s + ((size_t)y * SW + xx) * 8 + h;
    float sc[9];
#pragma unroll
    for (int dy = 0; dy < 3; dy++)
#pragma unroll
        for (int dx = 0; dx < 3; dx++)
            sc[dy * 3 + dx] = sp[((size_t)dy * SW + dx) * 8];

    float m = sc[0];
#pragma unroll
    for (int r = 1; r < 9; r++) m = fmaxf(m, sc[r]);
    float e[9], sum = 0.0f;
#pragma unroll
    for (int r = 0; r < 9; r++) { e[r] = __expf(sc[r] - m); sum += e[r]; }
    const float inv = 1.0f / sum;
    float w[9];
#pragma unroll
    for (int r = 0; r < 9; r++) w[r] = e[r] * inv;

    const float* vb = g_v + (size_t)(h * 32) * PVP + (size_t)y * PW + (xx + 1);
    float*       ob = out + (size_t)(h * 32) * NPIX + y * IMG_W + xx;
#pragma unroll 2
    for (int c = 0; c < 32; c++) {
        const float* vc = vb + (size_t)c * PVP;
        float acc = 0.0f;
#pragma unroll
        for (int r = 0; r < 9; r++)
            acc = fmaf(w[r], vc[(r / 3) * PW + (r % 3)], acc);
        ob[(size_t)c * NPIX] = acc;
    }
}

// ---------------------------------------------------------------- launch
extern "C" void kernel_launch(void* const* d_in, const int* in_sizes, int n_in,
                              void* d_out, int out_size)
{
    const float* x  = (const float*)d_in[0];
    const float* wq = (const float*)d_in[1];
    const float* wk = (const float*)d_in[2];
    const float* wv = (const float*)d_in[3];
    float* out = (float*)d_out;

    cudaFuncSetAttribute(proj_fused, cudaFuncAttributeMaxDynamicSharedMemorySize, SM_TOTAL);

    zero_borders<<<257, 256>>>();
    proj_fused<<<NPIX / 128, 512, SM_TOTAL>>>(x, wq, wk, wv);

    dim3 agrid(IMG_H, N_HEAD);
    attn_kernel<<<agrid, 192>>>(out);
}

// round 6
// speedup vs baseline: 2.6721x; 1.0511x over previous
#include <cuda_runtime.h>
#include <cstdint>

// ---------------------------------------------------------------- constants
#define C_IN   128
#define N_HEAD 8
#define IMG_H  192
#define IMG_W  192
#define NPIX   (IMG_H * IMG_W)     // 36864
#define PW     200                 // padded row stride (floats)
#define PH     194                 // padded rows
#define PVP    (PH * PW)           // 38800 floats per plane
#define TEMPER_INV (1.0f / 16.0f)

// scratch (device globals — allocation-free per harness rules)
__device__ float g_v[256 * PVP];        // 39.7 MB, padded planes, x-offset +2
__device__ float g_s[N_HEAD * PVP];     // 1.24 MB, padded planes, x-offset +2

// ---------------------------------------------------------------- SMEM map
#define SM_X     0            // X^T B-fragments: 64 KB
#define SM_W0    65536        // W A-fragments buffer 0: 64 KB
#define SM_W1    131072       // W A-fragments buffer 1: 64 KB
#define SM_TOTAL 196608

// ---------------------------------------------------------------- primitives
__device__ __forceinline__ uint32_t f2tf32(float f) {
    uint32_t r;
    asm("cvt.rna.tf32.f32 %0, %1;" : "=r"(r) : "f"(f));
    return r;
}

__device__ __forceinline__ void mma_tf32(float c[4], const uint32_t a[4],
                                         uint32_t b0, uint32_t b1) {
    asm volatile(
        "mma.sync.aligned.m16n8k8.row.col.f32.tf32.tf32.f32 "
        "{%0,%1,%2,%3}, {%4,%5,%6,%7}, {%8,%9}, {%0,%1,%2,%3};"
        : "+f"(c[0]), "+f"(c[1]), "+f"(c[2]), "+f"(c[3])
        : "r"(a[0]), "r"(a[1]), "r"(a[2]), "r"(a[3]), "r"(b0), "r"(b1));
}

// W[128x128] fp32 (k-contig) -> A-fragment-major smem (one uint4 per frag slot).
__device__ __forceinline__ void loadW_frag(const float* __restrict__ Wg,
                                           char* buf, int tid) {
    const int lane = tid & 31, kstep = tid >> 5;      // kstep 0..15
    const int r = lane >> 2, c = lane & 3;
#pragma unroll
    for (int rowgrp = 0; rowgrp < 8; rowgrp++) {
        const float* p = Wg + (rowgrp * 16 + r) * C_IN + kstep * 8 + c;
        uint32_t a0 = f2tf32(p[0]);
        uint32_t a1 = f2tf32(p[8 * C_IN]);
        uint32_t a2 = f2tf32(p[4]);
        uint32_t a3 = f2tf32(p[8 * C_IN + 4]);
        *(uint4*)(buf + ((rowgrp * 16 + kstep) * 32 + lane) * 16) =
            make_uint4(a0, a1, a2, a3);
    }
}

// X^T tile (128 pixels, 128 chans) -> B-fragment-major smem.
__device__ __forceinline__ void loadX_frag(const float* __restrict__ xt,
                                           char* buf, int tid) {
    const int lane = tid & 31, kstep = tid >> 5;
    const int n = lane >> 2, kc = lane & 3;
#pragma unroll
    for (int pixgrp = 0; pixgrp < 16; pixgrp++) {
        const int pix = pixgrp * 8 + n;
        const int ch  = kstep * 8 + kc;
        uint32_t b0 = f2tf32(xt[(size_t)ch * NPIX + pix]);
        uint32_t b1 = f2tf32(xt[(size_t)(ch + 4) * NPIX + pix]);
        *(uint2*)(buf + ((pixgrp * 16 + kstep) * 32 + lane) * 8) = make_uint2(b0, b1);
    }
}

// C[2][4][4] += A(Abuf)[128x128] @ B(Bbuf)[128pix x 128k]^T for this warp tile.
__device__ __forceinline__ void gemm_tf32(const char* Abuf, const char* Bbuf,
                                          float C[2][4][4],
                                          int wr, int wc, int lane) {
#pragma unroll 4
    for (int kstep = 0; kstep < 16; kstep++) {
        uint32_t a[2][4];
#pragma unroll
        for (int tm = 0; tm < 2; tm++)
            *(uint4*)a[tm] =
                *(const uint4*)(Abuf + (((wr * 2 + tm) * 16 + kstep) * 32 + lane) * 16);
        uint32_t b[4][2];
#pragma unroll
        for (int tn = 0; tn < 4; tn++)
            *(uint2*)b[tn] =
                *(const uint2*)(Bbuf + (((wc * 4 + tn) * 16 + kstep) * 32 + lane) * 8);
#pragma unroll
        for (int tm = 0; tm < 2; tm++)
#pragma unroll
            for (int tn = 0; tn < 4; tn++)
                mma_tf32(C[tm][tn], a[tm], b[tn][0], b[tn][1]);
    }
}

__device__ __forceinline__ void zeroC(float C[2][4][4]) {
#pragma unroll
    for (int i = 0; i < 2; i++)
#pragma unroll
        for (int j = 0; j < 4; j++)
#pragma unroll
            for (int m = 0; m < 4; m++) C[i][j][m] = 0.0f;
}

// fused score epilogue -> padded per-head s plane (x-offset +2)
__device__ __forceinline__ void epi_s(const float C0[2][4][4], const float C1[2][4][4],
                                      int h, int p0, int wc, int lane) {
#pragma unroll
    for (int tn = 0; tn < 4; tn++) {
        float s0 = 0.0f, s1 = 0.0f;
#pragma unroll
        for (int tm = 0; tm < 2; tm++) {
            s0 += C0[tm][tn][0] * C1[tm][tn][0] + C0[tm][tn][2] * C1[tm][tn][2];
            s1 += C0[tm][tn][1] * C1[tm][tn][1] + C0[tm][tn][3] * C1[tm][tn][3];
        }
#pragma unroll
        for (int d = 4; d < 32; d <<= 1) {
            s0 += __shfl_xor_sync(0xffffffffu, s0, d);
            s1 += __shfl_xor_sync(0xffffffffu, s1, d);
        }
        if (lane < 4) {
            const int pix = p0 + wc * 32 + tn * 8 + lane * 2;
            const int y = pix / IMG_W, xx = pix - y * IMG_W;     // xx even
            *(float2*)&g_s[(size_t)h * PVP + (size_t)(y + 1) * PW + (xx + 2)] =
                make_float2(s0 * TEMPER_INV, s1 * TEMPER_INV);
        }
    }
}

// v epilogue: padded channel planes (x-offset +2 keeps 8B alignment)
__device__ __forceinline__ void sto_v(const float C[2][4][4], int cb,
                                      int p0, int wr, int wc, int lane) {
#pragma unroll
    for (int tm = 0; tm < 2; tm++)
#pragma unroll
        for (int tn = 0; tn < 4; tn++) {
            const int chan = cb + wr * 32 + tm * 16 + (lane >> 2);
            const int pix  = p0 + wc * 32 + tn * 8 + (lane & 3) * 2;
            const int y = pix / IMG_W, xx = pix - y * IMG_W;     // xx even
            float* vp = g_v + (size_t)chan * PVP + (size_t)(y + 1) * PW + (xx + 2);
            *(float2*)vp = make_float2(C[tm][tn][0], C[tm][tn][1]);
            *(float2*)(vp + (size_t)8 * PVP) = make_float2(C[tm][tn][2], C[tm][tn][3]);
        }
}

// ---------------------------------------------------------------- kernel 1
// one CTA per 128-pixel tile; 6 double-buffered weight stages.
// First 264 CTAs additionally zero the padded borders (disjoint addresses;
// attn launches after this kernel completes, so ordering is guaranteed).
__global__ void __launch_bounds__(512, 1)
proj_fused(const float* __restrict__ x,
           const float* __restrict__ wq,
           const float* __restrict__ wk,
           const float* __restrict__ wv)
{
    extern __shared__ char smem[];
    const int tid  = threadIdx.x;
    const int lane = tid & 31;
    const int wid  = tid >> 5;
    const int wr   = wid >> 2;     // 32-channel row group
    const int wc   = wid & 3;      // 32-pixel col group
    const int p0   = blockIdx.x * 128;

    // ---- folded border zeroing (replaces the old zero_borders kernel)
    {
        const int bx = blockIdx.x;
        float* plane = (bx < 256) ? (g_v + (size_t)bx * PVP)
                     : (bx < 264) ? (g_s + (size_t)(bx - 256) * PVP)
                     : nullptr;
        if (plane) {
            if (tid < 200) {
                plane[tid] = 0.0f;
                plane[(size_t)193 * PW + tid] = 0.0f;
            } else if (tid >= 256 && tid < 448) {
                const int r = tid - 255;                 // 1..192
                plane[(size_t)r * PW + 1]   = 0.0f;
                plane[(size_t)r * PW + 194] = 0.0f;
            }
        }
    }

    loadX_frag(x + p0, smem + SM_X, tid);
    loadW_frag(wq, smem + SM_W0, tid);
    __syncthreads();

    float C0[2][4][4], C1[2][4][4];

    // stage 0: q chans 0..127  (buf0); prefetch wk0 -> buf1
    loadW_frag(wk, smem + SM_W1, tid);
    zeroC(C0);
    gemm_tf32(smem + SM_W0, smem + SM_X, C0, wr, wc, lane);
    __syncthreads();

    // stage 1: k chans 0..127  (buf1); prefetch wq1 -> buf0
    loadW_frag(wq + 16384, smem + SM_W0, tid);
    zeroC(C1);
    gemm_tf32(smem + SM_W1, smem + SM_X, C1, wr, wc, lane);
    epi_s(C0, C1, wr, p0, wc, lane);
    __syncthreads();

    // stage 2: q chans 128..255 (buf0); prefetch wk1 -> buf1
    loadW_frag(wk + 16384, smem + SM_W1, tid);
    zeroC(C0);
    gemm_tf32(smem + SM_W0, smem + SM_X, C0, wr, wc, lane);
    __syncthreads();

    // stage 3: k chans 128..255 (buf1); prefetch wv0 -> buf0
    loadW_frag(wv, smem + SM_W0, tid);
    zeroC(C1);
    gemm_tf32(smem + SM_W1, smem + SM_X, C1, wr, wc, lane);
    epi_s(C0, C1, 4 + wr, p0, wc, lane);
    __syncthreads();

    // stage 4: v chans 0..127 (buf0); prefetch wv1 -> buf1
    loadW_frag(wv + 16384, smem + SM_W1, tid);
    zeroC(C0);
    gemm_tf32(smem + SM_W0, smem + SM_X, C0, wr, wc, lane);
    sto_v(C0, 0, p0, wr, wc, lane);
    __syncthreads();

    // stage 5: v chans 128..255 (buf1)
    zeroC(C0);
    gemm_tf32(smem + SM_W1, smem + SM_X, C0, wr, wc, lane);
    sto_v(C0, 128, p0, wr, wc, lane);
}

// ---------------------------------------------------------------- kernel 2
// vectorized attn: each thread computes 4 consecutive pixels.
// s and v both live in padded planes (pixel p -> col p+2), so the 6-wide
// stencil window [p-1 .. p+4] is covered by two aligned float4 loads at
// cols px0 and px0+4 (tap j = i + dx + 1 in window coords).
__global__ void __launch_bounds__(192)
attn_kernel(float* __restrict__ out)
{
    const int tid = threadIdx.x;
    const int tx  = tid % 48;              // 48 threads per image row
    const int ty  = tid / 48;              // 4 rows per block
    const int y   = blockIdx.x * 4 + ty;
    const int h   = blockIdx.y;
    const int px0 = tx * 4;

    // ---- s window: 3 rows x 8 cols (scores pre-divided by 16 at write)
    float sf[3][8];
    {
        const float* sp = g_s + (size_t)h * PVP + (size_t)y * PW + px0;
#pragma unroll
        for (int dy = 0; dy < 3; dy++) {
            float4 a = *(const float4*)(sp + (size_t)dy * PW);
            float4 b = *(const float4*)(sp + (size_t)dy * PW + 4);
            sf[dy][0] = a.x; sf[dy][1] = a.y; sf[dy][2] = a.z; sf[dy][3] = a.w;
            sf[dy][4] = b.x; sf[dy][5] = b.y; sf[dy][6] = b.z; sf[dy][7] = b.w;
        }
    }

    // ---- softmax weights for the 4 pixels
    float w[4][9];
#pragma unroll
    for (int i = 0; i < 4; i++) {
        float m = sf[0][i + 1];
#pragma unroll
        for (int dy = 0; dy < 3; dy++)
#pragma unroll
            for (int dx = 0; dx < 3; dx++)
                m = fmaxf(m, sf[dy][i + dx + 1]);
        float sum = 0.0f;
#pragma unroll
        for (int dy = 0; dy < 3; dy++)
#pragma unroll
            for (int dx = 0; dx < 3; dx++) {
                float e = __expf(sf[dy][i + dx + 1] - m);
                w[i][dy * 3 + dx] = e;
                sum += e;
            }
        const float inv = 1.0f / sum;
#pragma unroll
        for (int r = 0; r < 9; r++) w[i][r] *= inv;
    }

    // ---- channel loop: 3x2 float4 loads per channel, 1 float4 store
    const float* vb = g_v + (size_t)(h * 32) * PVP + (size_t)y * PW + px0;
    float*       ob = out + (size_t)(h * 32) * NPIX + y * IMG_W + px0;
#pragma unroll 2
    for (int c = 0; c < 32; c++) {
        const float* vc = vb + (size_t)c * PVP;
        float vf[3][8];
#pragma unroll
        for (int dy = 0; dy < 3; dy++) {
            float4 a = *(const float4*)(vc + (size_t)dy * PW);
            float4 b = *(const float4*)(vc + (size_t)dy * PW + 4);
            vf[dy][0] = a.x; vf[dy][1] = a.y; vf[dy][2] = a.z; vf[dy][3] = a.w;
            vf[dy][4] = b.x; vf[dy][5] = b.y; vf[dy][6] = b.z; vf[dy][7] = b.w;
        }
        float4 o;
        float* op = (float*)&o;
#pragma unroll
        for (int i = 0; i < 4; i++) {
            float acc = 0.0f;
#pragma unroll
            for (int dy = 0; dy < 3; dy++)
#pragma unroll
                for (int dx = 0; dx < 3; dx++)
                    acc = fmaf(w[i][dy * 3 + dx], vf[dy][i + dx + 1], acc);
            op[i] = acc;
        }
        *(float4*)(ob + (size_t)c * NPIX) = o;
    }
}

// ---------------------------------------------------------------- launch
extern "C" void kernel_launch(void* const* d_in, const int* in_sizes, int n_in,
                              void* d_out, int out_size)
{
    const float* x  = (const float*)d_in[0];
    const float* wq = (const float*)d_in[1];
    const float* wk = (const float*)d_in[2];
    const float* wv = (const float*)d_in[3];
    float* out = (float*)d_out;

    cudaFuncSetAttribute(proj_fused, cudaFuncAttributeMaxDynamicSharedMemorySize, SM_TOTAL);

    proj_fused<<<NPIX / 128, 512, SM_TOTAL>>>(x, wq, wk, wv);

    dim3 agrid(IMG_H / 4, N_HEAD);           // 48 x 8
    attn_kernel<<<agrid, 192>>>(out);
}

// round 7
// speedup vs baseline: 2.7361x; 1.0240x over previous
#include <cuda_runtime.h>
#include <cstdint>

// ---------------------------------------------------------------- constants
#define C_IN   128
#define N_HEAD 8
#define IMG_H  192
#define IMG_W  192
#define NPIX   (IMG_H * IMG_W)     // 36864
#define PW     200                 // padded row stride (floats)
#define PH     194                 // padded rows
#define PVP    (PH * PW)           // 38800 floats per plane
#define TEMPER_INV (1.0f / 16.0f)

// scratch (device globals — allocation-free per harness rules)
__device__ float g_v[256 * PVP];        // 39.7 MB, padded planes, x-offset +2
__device__ float g_s[N_HEAD * PVP];     // 1.24 MB, padded planes, x-offset +2

// ---------------------------------------------------------------- SMEM map
#define SM_X     0            // X^T B-fragments: 64 KB
#define SM_W0    65536        // W A-fragments buffer 0: 64 KB
#define SM_W1    131072       // W A-fragments buffer 1: 64 KB
#define SM_TOTAL 196608

// ---------------------------------------------------------------- primitives
__device__ __forceinline__ uint32_t f2tf32(float f) {
    uint32_t r;
    asm("cvt.rna.tf32.f32 %0, %1;" : "=r"(r) : "f"(f));
    return r;
}

__device__ __forceinline__ void mma_tf32(float c[4], const uint32_t a[4],
                                         uint32_t b0, uint32_t b1) {
    asm volatile(
        "mma.sync.aligned.m16n8k8.row.col.f32.tf32.tf32.f32 "
        "{%0,%1,%2,%3}, {%4,%5,%6,%7}, {%8,%9}, {%0,%1,%2,%3};"
        : "+f"(c[0]), "+f"(c[1]), "+f"(c[2]), "+f"(c[3])
        : "r"(a[0]), "r"(a[1]), "r"(a[2]), "r"(a[3]), "r"(b0), "r"(b1));
}

// W[128x128] fp32 (k-contig) -> A-fragment-major smem (one uint4 per frag slot).
__device__ __forceinline__ void loadW_frag(const float* __restrict__ Wg,
                                           char* buf, int tid) {
    const int lane = tid & 31, kstep = tid >> 5;      // kstep 0..15
    const int r = lane >> 2, c = lane & 3;
#pragma unroll
    for (int rowgrp = 0; rowgrp < 8; rowgrp++) {
        const float* p = Wg + (rowgrp * 16 + r) * C_IN + kstep * 8 + c;
        uint32_t a0 = f2tf32(p[0]);
        uint32_t a1 = f2tf32(p[8 * C_IN]);
        uint32_t a2 = f2tf32(p[4]);
        uint32_t a3 = f2tf32(p[8 * C_IN + 4]);
        *(uint4*)(buf + ((rowgrp * 16 + kstep) * 32 + lane) * 16) =
            make_uint4(a0, a1, a2, a3);
    }
}

// X^T tile (128 pixels, 128 chans) -> B-fragment-major smem.
__device__ __forceinline__ void loadX_frag(const float* __restrict__ xt,
                                           char* buf, int tid) {
    const int lane = tid & 31, kstep = tid >> 5;
    const int n = lane >> 2, kc = lane & 3;
#pragma unroll
    for (int pixgrp = 0; pixgrp < 16; pixgrp++) {
        const int pix = pixgrp * 8 + n;
        const int ch  = kstep * 8 + kc;
        uint32_t b0 = f2tf32(xt[(size_t)ch * NPIX + pix]);
        uint32_t b1 = f2tf32(xt[(size_t)(ch + 4) * NPIX + pix]);
        *(uint2*)(buf + ((pixgrp * 16 + kstep) * 32 + lane) * 8) = make_uint2(b0, b1);
    }
}

// C[2][4][4] += A(Abuf)[128x128] @ B(Bbuf)[128pix x 128k]^T for this warp tile.
__device__ __forceinline__ void gemm_tf32(const char* Abuf, const char* Bbuf,
                                          float C[2][4][4],
                                          int wr, int wc, int lane) {
#pragma unroll 4
    for (int kstep = 0; kstep < 16; kstep++) {
        uint32_t a[2][4];
#pragma unroll
        for (int tm = 0; tm < 2; tm++)
            *(uint4*)a[tm] =
                *(const uint4*)(Abuf + (((wr * 2 + tm) * 16 + kstep) * 32 + lane) * 16);
        uint32_t b[4][2];
#pragma unroll
        for (int tn = 0; tn < 4; tn++)
            *(uint2*)b[tn] =
                *(const uint2*)(Bbuf + (((wc * 4 + tn) * 16 + kstep) * 32 + lane) * 8);
#pragma unroll
        for (int tm = 0; tm < 2; tm++)
#pragma unroll
            for (int tn = 0; tn < 4; tn++)
                mma_tf32(C[tm][tn], a[tm], b[tn][0], b[tn][1]);
    }
}

__device__ __forceinline__ void zeroC(float C[2][4][4]) {
#pragma unroll
    for (int i = 0; i < 2; i++)
#pragma unroll
        for (int j = 0; j < 4; j++)
#pragma unroll
            for (int m = 0; m < 4; m++) C[i][j][m] = 0.0f;
}

// fused score epilogue -> padded per-head s plane (x-offset +2)
__device__ __forceinline__ void epi_s(const float C0[2][4][4], const float C1[2][4][4],
                                      int h, int p0, int wc, int lane) {
#pragma unroll
    for (int tn = 0; tn < 4; tn++) {
        float s0 = 0.0f, s1 = 0.0f;
#pragma unroll
        for (int tm = 0; tm < 2; tm++) {
            s0 += C0[tm][tn][0] * C1[tm][tn][0] + C0[tm][tn][2] * C1[tm][tn][2];
            s1 += C0[tm][tn][1] * C1[tm][tn][1] + C0[tm][tn][3] * C1[tm][tn][3];
        }
#pragma unroll
        for (int d = 4; d < 32; d <<= 1) {
            s0 += __shfl_xor_sync(0xffffffffu, s0, d);
            s1 += __shfl_xor_sync(0xffffffffu, s1, d);
        }
        if (lane < 4) {
            const int pix = p0 + wc * 32 + tn * 8 + lane * 2;
            const int y = pix / IMG_W, xx = pix - y * IMG_W;     // xx even
            *(float2*)&g_s[(size_t)h * PVP + (size_t)(y + 1) * PW + (xx + 2)] =
                make_float2(s0 * TEMPER_INV, s1 * TEMPER_INV);
        }
    }
}

// v epilogue: padded channel planes (x-offset +2 keeps 8B alignment)
__device__ __forceinline__ void sto_v(const float C[2][4][4], int cb,
                                      int p0, int wr, int wc, int lane) {
#pragma unroll
    for (int tm = 0; tm < 2; tm++)
#pragma unroll
        for (int tn = 0; tn < 4; tn++) {
            const int chan = cb + wr * 32 + tm * 16 + (lane >> 2);
            const int pix  = p0 + wc * 32 + tn * 8 + (lane & 3) * 2;
            const int y = pix / IMG_W, xx = pix - y * IMG_W;     // xx even
            float* vp = g_v + (size_t)chan * PVP + (size_t)(y + 1) * PW + (xx + 2);
            *(float2*)vp = make_float2(C[tm][tn][0], C[tm][tn][1]);
            *(float2*)(vp + (size_t)8 * PVP) = make_float2(C[tm][tn][2], C[tm][tn][3]);
        }
}

// ---------------------------------------------------------------- kernel 1
// one CTA per 128-pixel tile; 6 double-buffered weight stages.
// First 264 CTAs additionally zero the padded borders (disjoint addresses;
// attn launches after this kernel completes, so ordering is guaranteed).
__global__ void __launch_bounds__(512, 1)
proj_fused(const float* __restrict__ x,
           const float* __restrict__ wq,
           const float* __restrict__ wk,
           const float* __restrict__ wv)
{
    extern __shared__ char smem[];
    const int tid  = threadIdx.x;
    const int lane = tid & 31;
    const int wid  = tid >> 5;
    const int wr   = wid >> 2;     // 32-channel row group
    const int wc   = wid & 3;      // 32-pixel col group
    const int p0   = blockIdx.x * 128;

    // ---- folded border zeroing (replaces a dedicated kernel)
    {
        const int bx = blockIdx.x;
        float* plane = (bx < 256) ? (g_v + (size_t)bx * PVP)
                     : (bx < 264) ? (g_s + (size_t)(bx - 256) * PVP)
                     : nullptr;
        if (plane) {
            if (tid < 200) {
                plane[tid] = 0.0f;
                plane[(size_t)193 * PW + tid] = 0.0f;
            } else if (tid >= 256 && tid < 448) {
                const int r = tid - 255;                 // 1..192
                plane[(size_t)r * PW + 1]   = 0.0f;
                plane[(size_t)r * PW + 194] = 0.0f;
            }
        }
    }

    loadX_frag(x + p0, smem + SM_X, tid);
    loadW_frag(wq, smem + SM_W0, tid);
    __syncthreads();

    float C0[2][4][4], C1[2][4][4];

    // stage 0: q chans 0..127  (buf0); prefetch wk0 -> buf1
    loadW_frag(wk, smem + SM_W1, tid);
    zeroC(C0);
    gemm_tf32(smem + SM_W0, smem + SM_X, C0, wr, wc, lane);
    __syncthreads();

    // stage 1: k chans 0..127  (buf1); prefetch wq1 -> buf0
    loadW_frag(wq + 16384, smem + SM_W0, tid);
    zeroC(C1);
    gemm_tf32(smem + SM_W1, smem + SM_X, C1, wr, wc, lane);
    epi_s(C0, C1, wr, p0, wc, lane);
    __syncthreads();

    // stage 2: q chans 128..255 (buf0); prefetch wk1 -> buf1
    loadW_frag(wk + 16384, smem + SM_W1, tid);
    zeroC(C0);
    gemm_tf32(smem + SM_W0, smem + SM_X, C0, wr, wc, lane);
    __syncthreads();

    // stage 3: k chans 128..255 (buf1); prefetch wv0 -> buf0
    loadW_frag(wv, smem + SM_W0, tid);
    zeroC(C1);
    gemm_tf32(smem + SM_W1, smem + SM_X, C1, wr, wc, lane);
    epi_s(C0, C1, 4 + wr, p0, wc, lane);
    __syncthreads();

    // stage 4: v chans 0..127 (buf0); prefetch wv1 -> buf1
    loadW_frag(wv + 16384, smem + SM_W1, tid);
    zeroC(C0);
    gemm_tf32(smem + SM_W0, smem + SM_X, C0, wr, wc, lane);
    sto_v(C0, 0, p0, wr, wc, lane);
    __syncthreads();

    // stage 5: v chans 128..255 (buf1)
    zeroC(C0);
    gemm_tf32(smem + SM_W1, smem + SM_X, C0, wr, wc, lane);
    sto_v(C0, 128, p0, wr, wc, lane);
}

// ---------------------------------------------------------------- kernel 2
// vectorized attn, channel-split for occupancy: grid (48, 8, 4).
// Each block handles 4 image rows x 8 of the head's 32 channels; softmax
// weights are recomputed per block (s loads are L2-resident, exp is cheap).
__global__ void __launch_bounds__(192)
attn_kernel(float* __restrict__ out)
{
    const int tid = threadIdx.x;
    const int tx  = tid % 48;              // 48 threads per image row
    const int ty  = tid / 48;              // 4 rows per block
    const int y   = blockIdx.x * 4 + ty;
    const int h   = blockIdx.y;
    const int cg  = blockIdx.z * 8;        // channel group base (0,8,16,24)
    const int px0 = tx * 4;

    // ---- s window: 3 rows x 8 cols (scores pre-divided by 16 at write)
    float sf[3][8];
    {
        const float* sp = g_s + (size_t)h * PVP + (size_t)y * PW + px0;
#pragma unroll
        for (int dy = 0; dy < 3; dy++) {
            float4 a = *(const float4*)(sp + (size_t)dy * PW);
            float4 b = *(const float4*)(sp + (size_t)dy * PW + 4);
            sf[dy][0] = a.x; sf[dy][1] = a.y; sf[dy][2] = a.z; sf[dy][3] = a.w;
            sf[dy][4] = b.x; sf[dy][5] = b.y; sf[dy][6] = b.z; sf[dy][7] = b.w;
        }
    }

    // ---- softmax weights for the 4 pixels
    float w[4][9];
#pragma unroll
    for (int i = 0; i < 4; i++) {
        float m = sf[0][i + 1];
#pragma unroll
        for (int dy = 0; dy < 3; dy++)
#pragma unroll
            for (int dx = 0; dx < 3; dx++)
                m = fmaxf(m, sf[dy][i + dx + 1]);
        float sum = 0.0f;
#pragma unroll
        for (int dy = 0; dy < 3; dy++)
#pragma unroll
            for (int dx = 0; dx < 3; dx++) {
                float e = __expf(sf[dy][i + dx + 1] - m);
                w[i][dy * 3 + dx] = e;
                sum += e;
            }
        const float inv = 1.0f / sum;
#pragma unroll
        for (int r = 0; r < 9; r++) w[i][r] *= inv;
    }

    // ---- channel loop (8 channels): 3x2 float4 loads each, 1 float4 store
    const float* vb = g_v + (size_t)(h * 32 + cg) * PVP + (size_t)y * PW + px0;
    float*       ob = out + (size_t)(h * 32 + cg) * NPIX + y * IMG_W + px0;
#pragma unroll 2
    for (int c = 0; c < 8; c++) {
        const float* vc = vb + (size_t)c * PVP;
        float vf[3][8];
#pragma unroll
        for (int dy = 0; dy < 3; dy++) {
            float4 a = *(const float4*)(vc + (size_t)dy * PW);
            float4 b = *(const float4*)(vc + (size_t)dy * PW + 4);
            vf[dy][0] = a.x; vf[dy][1] = a.y; vf[dy][2] = a.z; vf[dy][3] = a.w;
            vf[dy][4] = b.x; vf[dy][5] = b.y; vf[dy][6] = b.z; vf[dy][7] = b.w;
        }
        float4 o;
        float* op = (float*)&o;
#pragma unroll
        for (int i = 0; i < 4; i++) {
            float acc = 0.0f;
#pragma unroll
            for (int dy = 0; dy < 3; dy++)
#pragma unroll
                for (int dx = 0; dx < 3; dx++)
                    acc = fmaf(w[i][dy * 3 + dx], vf[dy][i + dx + 1], acc);
            op[i] = acc;
        }
        *(float4*)(ob + (size_t)c * NPIX) = o;
    }
}

// ---------------------------------------------------------------- launch
extern "C" void kernel_launch(void* const* d_in, const int* in_sizes, int n_in,
                              void* d_out, int out_size)
{
    const float* x  = (const float*)d_in[0];
    const float* wq = (const float*)d_in[1];
    const float* wk = (const float*)d_in[2];
    const float* wv = (const float*)d_in[3];
    float* out = (float*)d_out;

    cudaFuncSetAttribute(proj_fused, cudaFuncAttributeMaxDynamicSharedMemorySize, SM_TOTAL);

    proj_fused<<<NPIX / 128, 512, SM_TOTAL>>>(x, wq, wk, wv);

    dim3 agrid(IMG_H / 4, N_HEAD, 4);        // 48 x 8 x 4 = 1536 blocks
    attn_kernel<<<agrid, 192>>>(out);
}

// round 8
// speedup vs baseline: 3.2267x; 1.1793x over previous
#include <cuda_runtime.h>
#include <cstdint>

// ---------------------------------------------------------------- constants
#define C_IN   128
#define N_HEAD 8
#define IMG_H  192
#define IMG_W  192
#define NPIX   (IMG_H * IMG_W)     // 36864
#define PW     200                 // padded row stride (floats)
#define PH     194                 // padded rows
#define PVP    (PH * PW)           // 38800 floats per plane
#define TEMPER_INV (1.0f / 16.0f)

// scratch (device globals — allocation-free per harness rules)
__device__ float g_v[256 * PVP];        // 39.7 MB, padded planes, x-offset +2
__device__ float g_s[N_HEAD * PVP];     // 1.24 MB, padded planes, x-offset +2
__device__ uint4 g_wfrag[6 * 4096];     // 384 KB: W in A-fragment form, stage order

// ---------------------------------------------------------------- SMEM map
#define SM_X     0            // X^T B-fragments: 64 KB
#define SM_W0    65536        // W A-fragments buffer 0: 64 KB
#define SM_W1    131072       // W A-fragments buffer 1: 64 KB
#define SM_TOTAL 196608

// ---------------------------------------------------------------- primitives
__device__ __forceinline__ uint32_t f2tf32(float f) {
    uint32_t r;
    asm("cvt.rna.tf32.f32 %0, %1;" : "=r"(r) : "f"(f));
    return r;
}

__device__ __forceinline__ void mma_tf32(float c[4], const uint32_t a[4],
                                         uint32_t b0, uint32_t b1) {
    asm volatile(
        "mma.sync.aligned.m16n8k8.row.col.f32.tf32.tf32.f32 "
        "{%0,%1,%2,%3}, {%4,%5,%6,%7}, {%8,%9}, {%0,%1,%2,%3};"
        : "+f"(c[0]), "+f"(c[1]), "+f"(c[2]), "+f"(c[3])
        : "r"(a[0]), "r"(a[1]), "r"(a[2]), "r"(a[3]), "r"(b0), "r"(b1));
}

// X^T tile (128 pixels, 128 chans) -> B-fragment-major smem.
__device__ __forceinline__ void loadX_frag(const float* __restrict__ xt,
                                           char* buf, int tid) {
    const int lane = tid & 31, kstep = tid >> 5;
    const int n = lane >> 2, kc = lane & 3;
#pragma unroll
    for (int pixgrp = 0; pixgrp < 16; pixgrp++) {
        const int pix = pixgrp * 8 + n;
        const int ch  = kstep * 8 + kc;
        uint32_t b0 = f2tf32(xt[(size_t)ch * NPIX + pix]);
        uint32_t b1 = f2tf32(xt[(size_t)(ch + 4) * NPIX + pix]);
        *(uint2*)(buf + ((pixgrp * 16 + kstep) * 32 + lane) * 8) = make_uint2(b0, b1);
    }
}

// stage W fragments: plain coalesced copy from pre-converted global array
__device__ __forceinline__ void loadW_copy(int s, char* buf, int tid) {
    const uint4* __restrict__ src = g_wfrag + s * 4096;
    uint4* dst = (uint4*)buf;
#pragma unroll
    for (int i = 0; i < 8; i++)
        dst[tid + i * 512] = src[tid + i * 512];
}

// C[2][4][4] += A(Abuf)[128x128] @ B(Bbuf)[128pix x 128k]^T for this warp tile.
__device__ __forceinline__ void gemm_tf32(const char* Abuf, const char* Bbuf,
                                          float C[2][4][4],
                                          int wr, int wc, int lane) {
#pragma unroll 4
    for (int kstep = 0; kstep < 16; kstep++) {
        uint32_t a[2][4];
#pragma unroll
        for (int tm = 0; tm < 2; tm++)
            *(uint4*)a[tm] =
                *(const uint4*)(Abuf + (((wr * 2 + tm) * 16 + kstep) * 32 + lane) * 16);
        uint32_t b[4][2];
#pragma unroll
        for (int tn = 0; tn < 4; tn++)
            *(uint2*)b[tn] =
                *(const uint2*)(Bbuf + (((wc * 4 + tn) * 16 + kstep) * 32 + lane) * 8);
#pragma unroll
        for (int tm = 0; tm < 2; tm++)
#pragma unroll
            for (int tn = 0; tn < 4; tn++)
                mma_tf32(C[tm][tn], a[tm], b[tn][0], b[tn][1]);
    }
}

__device__ __forceinline__ void zeroC(float C[2][4][4]) {
#pragma unroll
    for (int i = 0; i < 2; i++)
#pragma unroll
        for (int j = 0; j < 4; j++)
#pragma unroll
            for (int m = 0; m < 4; m++) C[i][j][m] = 0.0f;
}

// fused score epilogue -> padded per-head s plane (x-offset +2)
__device__ __forceinline__ void epi_s(const float C0[2][4][4], const float C1[2][4][4],
                                      int h, int p0, int wc, int lane) {
#pragma unroll
    for (int tn = 0; tn < 4; tn++) {
        float s0 = 0.0f, s1 = 0.0f;
#pragma unroll
        for (int tm = 0; tm < 2; tm++) {
            s0 += C0[tm][tn][0] * C1[tm][tn][0] + C0[tm][tn][2] * C1[tm][tn][2];
            s1 += C0[tm][tn][1] * C1[tm][tn][1] + C0[tm][tn][3] * C1[tm][tn][3];
        }
#pragma unroll
        for (int d = 4; d < 32; d <<= 1) {
            s0 += __shfl_xor_sync(0xffffffffu, s0, d);
            s1 += __shfl_xor_sync(0xffffffffu, s1, d);
        }
        if (lane < 4) {
            const int pix = p0 + wc * 32 + tn * 8 + lane * 2;
            const int y = pix / IMG_W, xx = pix - y * IMG_W;     // xx even
            *(float2*)&g_s[(size_t)h * PVP + (size_t)(y + 1) * PW + (xx + 2)] =
                make_float2(s0 * TEMPER_INV, s1 * TEMPER_INV);
        }
    }
}

// v epilogue: padded channel planes (x-offset +2 keeps 8B alignment)
__device__ __forceinline__ void sto_v(const float C[2][4][4], int cb,
                                      int p0, int wr, int wc, int lane) {
#pragma unroll
    for (int tm = 0; tm < 2; tm++)
#pragma unroll
        for (int tn = 0; tn < 4; tn++) {
            const int chan = cb + wr * 32 + tm * 16 + (lane >> 2);
            const int pix  = p0 + wc * 32 + tn * 8 + (lane & 3) * 2;
            const int y = pix / IMG_W, xx = pix - y * IMG_W;     // xx even
            float* vp = g_v + (size_t)chan * PVP + (size_t)(y + 1) * PW + (xx + 2);
            *(float2*)vp = make_float2(C[tm][tn][0], C[tm][tn][1]);
            *(float2*)(vp + (size_t)8 * PVP) = make_float2(C[tm][tn][2], C[tm][tn][3]);
        }
}

// ---------------------------------------------------------------- kernel 0
// W fp32 -> tf32 A-fragment array, stage order:
//   s=0: wq[0:128]  s=1: wk[0:128]  s=2: wq[128:256]
//   s=3: wk[128:256]  s=4: wv[0:128]  s=5: wv[128:256]
__global__ void __launch_bounds__(512)
prep_w(const float* __restrict__ wq,
       const float* __restrict__ wk,
       const float* __restrict__ wv)
{
    const int s = blockIdx.x;            // 0..5
    const int rowgrp = blockIdx.y;       // 0..7
    const float* mat = (s == 0 || s == 2) ? wq : (s == 1 || s == 3) ? wk : wv;
    const int off = (s == 2 || s == 3 || s == 5) ? 16384 : 0;

    const int tid = threadIdx.x;
    const int lane = tid & 31, kstep = tid >> 5;
    const int r = lane >> 2, c = lane & 3;

    const float* p = mat + off + (rowgrp * 16 + r) * C_IN + kstep * 8 + c;
    g_wfrag[s * 4096 + (rowgrp * 16 + kstep) * 32 + lane] =
        make_uint4(f2tf32(p[0]), f2tf32(p[8 * C_IN]),
                   f2tf32(p[4]), f2tf32(p[8 * C_IN + 4]));
}

// ---------------------------------------------------------------- kernel 1
// one CTA per 128-pixel tile; 6 double-buffered weight stages (copies of
// pre-converted fragments). First 264 CTAs also zero the padded borders.
__global__ void __launch_bounds__(512, 1)
proj_fused(const float* __restrict__ x,
           const float* __restrict__ wq,
           const float* __restrict__ wk,
           const float* __restrict__ wv)
{
    extern __shared__ char smem[];
    const int tid  = threadIdx.x;
    const int lane = tid & 31;
    const int wid  = tid >> 5;
    const int wr   = wid >> 2;     // 32-channel row group
    const int wc   = wid & 3;      // 32-pixel col group
    const int p0   = blockIdx.x * 128;

    // ---- folded border zeroing
    {
        const int bx = blockIdx.x;
        float* plane = (bx < 256) ? (g_v + (size_t)bx * PVP)
                     : (bx < 264) ? (g_s + (size_t)(bx - 256) * PVP)
                     : nullptr;
        if (plane) {
            if (tid < 200) {
                plane[tid] = 0.0f;
                plane[(size_t)193 * PW + tid] = 0.0f;
            } else if (tid >= 256 && tid < 448) {
                const int r = tid - 255;                 // 1..192
                plane[(size_t)r * PW + 1]   = 0.0f;
                plane[(size_t)r * PW + 194] = 0.0f;
            }
        }
    }

    loadX_frag(x + p0, smem + SM_X, tid);
    loadW_copy(0, smem + SM_W0, tid);
    __syncthreads();

    float C0[2][4][4], C1[2][4][4];

    // stage 0: q chans 0..127  (buf0); prefetch stage1 -> buf1
    loadW_copy(1, smem + SM_W1, tid);
    zeroC(C0);
    gemm_tf32(smem + SM_W0, smem + SM_X, C0, wr, wc, lane);
    __syncthreads();

    // stage 1: k chans 0..127  (buf1); prefetch stage2 -> buf0
    loadW_copy(2, smem + SM_W0, tid);
    zeroC(C1);
    gemm_tf32(smem + SM_W1, smem + SM_X, C1, wr, wc, lane);
    epi_s(C0, C1, wr, p0, wc, lane);
    __syncthreads();

    // stage 2: q chans 128..255 (buf0); prefetch stage3 -> buf1
    loadW_copy(3, smem + SM_W1, tid);
    zeroC(C0);
    gemm_tf32(smem + SM_W0, smem + SM_X, C0, wr, wc, lane);
    __syncthreads();

    // stage 3: k chans 128..255 (buf1); prefetch stage4 -> buf0
    loadW_copy(4, smem + SM_W0, tid);
    zeroC(C1);
    gemm_tf32(smem + SM_W1, smem + SM_X, C1, wr, wc, lane);
    epi_s(C0, C1, 4 + wr, p0, wc, lane);
    __syncthreads();

    // stage 4: v chans 0..127 (buf0); prefetch stage5 -> buf1
    loadW_copy(5, smem + SM_W1, tid);
    zeroC(C0);
    gemm_tf32(smem + SM_W0, smem + SM_X, C0, wr, wc, lane);
    sto_v(C0, 0, p0, wr, wc, lane);
    __syncthreads();

    // stage 5: v chans 128..255 (buf1)
    zeroC(C0);
    gemm_tf32(smem + SM_W1, smem + SM_X, C0, wr, wc, lane);
    sto_v(C0, 128, p0, wr, wc, lane);
}

// ---------------------------------------------------------------- kernel 2
// vectorized attn, channel-split for occupancy: grid (48, 8, 4).
__global__ void __launch_bounds__(192)
attn_kernel(float* __restrict__ out)
{
    const int tid = threadIdx.x;
    const int tx  = tid % 48;              // 48 threads per image row
    const int ty  = tid / 48;              // 4 rows per block
    const int y   = blockIdx.x * 4 + ty;
    const int h   = blockIdx.y;
    const int cg  = blockIdx.z * 8;        // channel group base
    const int px0 = tx * 4;

    // ---- s window: 3 rows x 8 cols
    float sf[3][8];
    {
        const float* sp = g_s + (size_t)h * PVP + (size_t)y * PW + px0;
#pragma unroll
        for (int dy = 0; dy < 3; dy++) {
            float4 a = *(const float4*)(sp + (size_t)dy * PW);
            float4 b = *(const float4*)(sp + (size_t)dy * PW + 4);
            sf[dy][0] = a.x; sf[dy][1] = a.y; sf[dy][2] = a.z; sf[dy][3] = a.w;
            sf[dy][4] = b.x; sf[dy][5] = b.y; sf[dy][6] = b.z; sf[dy][7] = b.w;
        }
    }

    // ---- softmax weights for the 4 pixels
    float w[4][9];
#pragma unroll
    for (int i = 0; i < 4; i++) {
        float m = sf[0][i + 1];
#pragma unroll
        for (int dy = 0; dy < 3; dy++)
#pragma unroll
            for (int dx = 0; dx < 3; dx++)
                m = fmaxf(m, sf[dy][i + dx + 1]);
        float sum = 0.0f;
#pragma unroll
        for (int dy = 0; dy < 3; dy++)
#pragma unroll
            for (int dx = 0; dx < 3; dx++) {
                float e = __expf(sf[dy][i + dx + 1] - m);
                w[i][dy * 3 + dx] = e;
                sum += e;
            }
        const float inv = 1.0f / sum;
#pragma unroll
        for (int r = 0; r < 9; r++) w[i][r] *= inv;
    }

    // ---- channel loop (8 channels)
    const float* vb = g_v + (size_t)(h * 32 + cg) * PVP + (size_t)y * PW + px0;
    float*       ob = out + (size_t)(h * 32 + cg) * NPIX + y * IMG_W + px0;
#pragma unroll 2
    for (int c = 0; c < 8; c++) {
        const float* vc = vb + (size_t)c * PVP;
        float vf[3][8];
#pragma unroll
        for (int dy = 0; dy < 3; dy++) {
            float4 a = *(const float4*)(vc + (size_t)dy * PW);
            float4 b = *(const float4*)(vc + (size_t)dy * PW + 4);
            vf[dy][0] = a.x; vf[dy][1] = a.y; vf[dy][2] = a.z; vf[dy][3] = a.w;
            vf[dy][4] = b.x; vf[dy][5] = b.y; vf[dy][6] = b.z; vf[dy][7] = b.w;
        }
        float4 o;
        float* op = (float*)&o;
#pragma unroll
        for (int i = 0; i < 4; i++) {
            float acc = 0.0f;
#pragma unroll
            for (int dy = 0; dy < 3; dy++)
#pragma unroll
                for (int dx = 0; dx < 3; dx++)
                    acc = fmaf(w[i][dy * 3 + dx], vf[dy][i + dx + 1], acc);
            op[i] = acc;
        }
        *(float4*)(ob + (size_t)c * NPIX) = o;
    }
}

// ---------------------------------------------------------------- kernel 3
// no-op: pads the per-iteration launch count to 4 so ncu's "-s 5 -c 1"
// (launch index 5 = 5 mod 4 = 1) captures proj_fused next profile.
__global__ void noop_kernel() {}

// ---------------------------------------------------------------- launch
extern "C" void kernel_launch(void* const* d_in, const int* in_sizes, int n_in,
                              void* d_out, int out_size)
{
    const float* x  = (const float*)d_in[0];
    const float* wq = (const float*)d_in[1];
    const float* wk = (const float*)d_in[2];
    const float* wv = (const float*)d_in[3];
    float* out = (float*)d_out;

    cudaFuncSetAttribute(proj_fused, cudaFuncAttributeMaxDynamicSharedMemorySize, SM_TOTAL);

    dim3 wgrid(6, 8);
    prep_w<<<wgrid, 512>>>(wq, wk, wv);

    proj_fused<<<NPIX / 128, 512, SM_TOTAL>>>(x, wq, wk, wv);

    dim3 agrid(IMG_H / 4, N_HEAD, 4);        // 48 x 8 x 4 = 1536 blocks
    attn_kernel<<<agrid, 192>>>(out);

    noop_kernel<<<1, 32>>>();
}